// round 1
// baseline (speedup 1.0000x reference)
#include <cuda_runtime.h>
#include <stdint.h>
#include <math.h>

// Problem dims (fixed by dataset): N=100000 nodes, C=32 classes, E=3.2M edges
#define NMAX 100000
#define CC 32

// Scratch (device globals; no allocation allowed)
__device__ float g_p[NMAX * CC];      // masked softmax probs (12.8MB)
__device__ int2  g_info[NMAX];        // .x = bitcast(dinv), .y = label (or -1 if unmasked)
__device__ float g_deg[NMAX];
__device__ float g_H[CC * CC];        // ym^T @ nodeH accumulator
__device__ float g_cnt[CC];
__device__ int   g_maskmode;          // 0=uint8, 1=float32, 2=int32

// ---------------------------------------------------------------------------
// Mask dtype detection: a byte-mask viewed as int32/float32 can't be all {0,1}
// / {0.0f,1.0f}, and vice versa. Deterministic given fixed inputs.
__global__ void detect_mask_kernel(const void* mask) {
    if (threadIdx.x == 0 && blockIdx.x == 0) {
        const int*   mi = (const int*)mask;
        const float* mf = (const float*)mask;
        bool isInt = true, isFloat = true;
        for (int k = 0; k < 64; k++) {
            int v = mi[k];
            if (v != 0 && v != 1) isInt = false;
            float f = mf[k];
            if (f != 0.0f && f != 1.0f) isFloat = false;
        }
        g_maskmode = isInt ? 2 : (isFloat ? 1 : 0);
    }
}

__device__ __forceinline__ bool get_mask(const void* m, int r) {
    int mm = g_maskmode;
    if (mm == 0) return ((const uint8_t*)m)[r] != 0;
    if (mm == 2) return ((const int*)m)[r] != 0;
    return ((const float*)m)[r] != 0.0f;
}

// ---------------------------------------------------------------------------
__global__ void zero_kernel(int n) {
    int i = blockIdx.x * blockDim.x + threadIdx.x;
    if (i < n) g_deg[i] = 0.0f;
    if (i < CC * CC) g_H[i] = 0.0f;
    if (i < CC) g_cnt[i] = 0.0f;
}

// deg = segment_sum(w, row) with self-loops (weight 1)
__global__ void deg_kernel(const int* __restrict__ row,
                           const float* __restrict__ w, int E, int N) {
    int i = blockIdx.x * blockDim.x + threadIdx.x;
    if (i < E) {
        atomicAdd(&g_deg[row[i]], w[i]);
    } else if (i < E + N) {
        atomicAdd(&g_deg[i - E], 1.0f);
    }
}

// One warp per node: softmax(inputs) -> mask-replace by y; label + dinv + cnt
__global__ void node_kernel(const float* __restrict__ inp,
                            const float* __restrict__ y,
                            const void* mask, int N) {
    int gw   = (blockIdx.x * blockDim.x + threadIdx.x) >> 5;
    int lane = threadIdx.x & 31;
    if (gw >= N) return;

    float x = inp[gw * CC + lane];
    float mx = x;
    #pragma unroll
    for (int o = 16; o; o >>= 1) mx = fmaxf(mx, __shfl_xor_sync(0xffffffffu, mx, o));
    float ex = __expf(x - mx);
    float s = ex;
    #pragma unroll
    for (int o = 16; o; o >>= 1) s += __shfl_xor_sync(0xffffffffu, s, o);
    float p = ex / s;

    float yv = y[gw * CC + lane];
    bool mk = get_mask(mask, gw);   // uniform across warp
    int lab = -1;
    if (mk) {
        p = yv;
        unsigned b = __ballot_sync(0xffffffffu, yv > 0.5f);
        lab = __ffs(b) - 1;
    }
    g_p[gw * CC + lane] = p;

    if (lane == 0) {
        float d  = g_deg[gw];
        float di = (d > 0.0f) ? rsqrtf(d) : 0.0f;
        g_info[gw] = make_int2(__float_as_int(di), lab);
        if (lab >= 0) atomicAdd(&g_cnt[lab], 1.0f);
    }
}

// Edge kernel: warp-per-edge accumulation into per-warp private smem H tiles.
// Entries [0,E) are edges; [E,E+N) are self-loops (r=c, w=1).
__global__ void edge_kernel(const int* __restrict__ row,
                            const int* __restrict__ col,
                            const float* __restrict__ w, int E, int N) {
    __shared__ float sH[8][CC * 33];
    int wid  = threadIdx.x >> 5;
    int lane = threadIdx.x & 31;
    float* mh = sH[wid];

    for (int k = threadIdx.x; k < 8 * CC * 33; k += blockDim.x)
        ((float*)sH)[k] = 0.0f;
    __syncthreads();

    int total  = E + N;
    int gw     = blockIdx.x * (blockDim.x >> 5) + wid;
    int stride = gridDim.x * (blockDim.x >> 5);

    for (int base = gw * 32; base < total; base += stride * 32) {
        int e = base + lane;
        int c = 0, lab = -1;
        float v = 0.0f;
        if (e < total) {
            int r; float wt;
            if (e < E) { r = row[e]; c = col[e]; wt = w[e]; }
            else       { r = e - E; c = r;      wt = 1.0f; }
            int2 ir = g_info[r];
            lab = ir.y;
            if (lab >= 0) {
                float dc = __int_as_float(g_info[c].x);
                v = __int_as_float(ir.x) * wt * dc;
            }
        }
        unsigned act = __ballot_sync(0xffffffffu, lab >= 0);
        while (act) {
            int s = __ffs(act) - 1;
            act &= act - 1;
            int   a  = __shfl_sync(0xffffffffu, lab, s);
            int   cs = __shfl_sync(0xffffffffu, c,   s);
            float vs = __shfl_sync(0xffffffffu, v,   s);
            float pv = g_p[cs * CC + lane];       // coalesced 128B
            mh[a * 33 + lane] += vs * pv;         // private tile, no atomics
        }
    }
    __syncthreads();

    for (int k = threadIdx.x; k < CC * CC; k += blockDim.x) {
        int a = k >> 5, j = k & 31;
        float s = 0.0f;
        #pragma unroll
        for (int ww = 0; ww < 8; ww++) s += sH[ww][a * 33 + j];
        atomicAdd(&g_H[k], s);
    }
}

// Final: H = acc/cnt, NaN fixups, Sinkhorn loop (converges ~<100 iters; the
// reference's 3000 iterations are a fixed point after convergence).
__global__ void final_kernel(float* __restrict__ out) {
    __shared__ float sm[CC * 33];
    __shared__ float sred[CC];
    __shared__ int   sflag;

    int i = threadIdx.x >> 5;   // row
    int j = threadIdx.x & 31;   // col (lane)

    float h = g_H[i * CC + j] / g_cnt[i];   // 0/0 -> NaN if empty class

    // Fixup 1: H = where(isnan(H), H^T, H)   (uses ORIGINAL H both sides)
    sm[j * 33 + i] = h;         // sm[x*33+y] = H[y][x]
    __syncthreads();
    float ht = sm[i * 33 + j];  // = H[j][i]
    if (isnan(h)) h = ht;
    __syncthreads();

    // Fixup 2: H0 = where(Hn,0,H); miss = (1-rowsum(H0))/rowcount(Hn); H = where(Hn,miss,H0)
    bool n2 = isnan(h);
    float h0 = n2 ? 0.0f : h;
    float rs = h0;
    float rn = n2 ? 1.0f : 0.0f;
    #pragma unroll
    for (int o = 16; o; o >>= 1) {
        rs += __shfl_xor_sync(0xffffffffu, rs, o);
        rn += __shfl_xor_sync(0xffffffffu, rn, o);
    }
    float miss = (1.0f - rs) / rn;  // inf if rn==0, but then unused
    h = n2 ? miss : h0;

    // Sinkhorn: col-normalize then row-normalize, to convergence (cap 3000)
    float hsave = h;
    for (int it = 0; it < 3000; it++) {
        sm[i * 33 + j] = h;                 // row-major snapshot
        __syncthreads();
        float vc = sm[j * 33 + i];          // warp i owns column i; vc=H[j][i]
        float cs = vc;
        #pragma unroll
        for (int o = 16; o; o >>= 1) cs += __shfl_xor_sync(0xffffffffu, cs, o);
        vc /= cs;
        sm[j * 33 + i] = vc;
        __syncthreads();
        h = sm[i * 33 + j];                 // back to row ownership
        float rs2 = h;
        #pragma unroll
        for (int o = 16; o; o >>= 1) rs2 += __shfl_xor_sync(0xffffffffu, rs2, o);
        h /= rs2;

        if ((it & 7) == 7) {
            float d = fabsf(h - hsave);
            #pragma unroll
            for (int o = 16; o; o >>= 1) d = fmaxf(d, __shfl_xor_sync(0xffffffffu, d, o));
            if (j == 0) sred[i] = d;
            __syncthreads();
            if (threadIdx.x == 0) {
                float m = 0.0f;
                for (int k = 0; k < CC; k++) m = fmaxf(m, sred[k]);
                sflag = (m < 1e-10f) ? 1 : 0;
            }
            __syncthreads();
            if (sflag) break;
            hsave = h;
        }
    }
    out[i * CC + j] = h;
}

// ---------------------------------------------------------------------------
extern "C" void kernel_launch(void* const* d_in, const int* in_sizes, int n_in,
                              void* d_out, int out_size) {
    const int*   ei   = (const int*)d_in[0];    // edge_index (2,E)
    const float* ew   = (const float*)d_in[1];  // edge_weight (E,)
    const float* inp  = (const float*)d_in[2];  // inputs (N,32)
    const float* y    = (const float*)d_in[3];  // y (N,32)
    const void*  mask = d_in[4];                // sample_mask (N,)

    int E = in_sizes[1];
    int N = in_sizes[2] / CC;
    const int* rowp = ei;
    const int* colp = ei + E;

    detect_mask_kernel<<<1, 32>>>(mask);
    zero_kernel<<<(N + 255) / 256, 256>>>(N);
    deg_kernel<<<(E + N + 255) / 256, 256>>>(rowp, ew, E, N);
    node_kernel<<<(N + 7) / 8, 256>>>(inp, y, mask, N);
    edge_kernel<<<888, 256>>>(rowp, colp, ew, E, N);
    final_kernel<<<1, 1024>>>((float*)d_out);
}

// round 2
// speedup vs baseline: 1.3124x; 1.3124x over previous
#include <cuda_runtime.h>
#include <stdint.h>
#include <math.h>

// Problem dims (fixed by dataset): N=100000 nodes, C=32 classes, E=3.2M edges
#define NMAX 100000
#define CC 32

// Scratch (device globals; no allocation allowed)
__device__ float g_p[NMAX * CC];      // masked softmax probs (12.8MB)
__device__ int2  g_info[NMAX];        // .x = bitcast(dinv), .y = label (or -1 if unmasked)
__device__ float g_deg[NMAX];
__device__ float g_H[CC * CC];        // ym^T @ nodeH accumulator
__device__ float g_cnt[CC];
__device__ int   g_maskmode;          // 0=uint8, 1=float32, 2=int32

__device__ __forceinline__ bool get_mask(const void* m, int r, int mm) {
    if (mm == 0) return ((const uint8_t*)m)[r] != 0;
    if (mm == 2) return ((const int*)m)[r] != 0;
    return ((const float*)m)[r] != 0.0f;
}

// ---------------------------------------------------------------------------
// zero scratch + detect mask dtype (byte-mask viewed as int32/float32 can't be
// all {0,1}/{0.0f,1.0f}, and vice versa). Deterministic given fixed inputs.
__global__ void zero_detect_kernel(const void* mask, int n) {
    int i = blockIdx.x * blockDim.x + threadIdx.x;
    if (i < n) g_deg[i] = 0.0f;
    if (i < CC * CC) g_H[i] = 0.0f;
    if (i < CC) g_cnt[i] = 0.0f;
    if (i == 0) {
        const int*   mi = (const int*)mask;
        const float* mf = (const float*)mask;
        bool isInt = true, isFloat = true;
        for (int k = 0; k < 64; k++) {
            int v = mi[k];
            if (v != 0 && v != 1) isInt = false;
            float f = mf[k];
            if (f != 0.0f && f != 1.0f) isFloat = false;
        }
        g_maskmode = isInt ? 2 : (isFloat ? 1 : 0);
    }
}

// deg = segment_sum(w, row) with self-loops (weight 1)
__global__ void deg_kernel(const int* __restrict__ row,
                           const float* __restrict__ w, int E, int N) {
    int i = blockIdx.x * blockDim.x + threadIdx.x;
    if (i < E) {
        atomicAdd(&g_deg[row[i]], w[i]);
    } else if (i < E + N) {
        atomicAdd(&g_deg[i - E], 1.0f);
    }
}

// 4 threads per node, 8 floats (2x float4) each: softmax -> mask-replace by y.
// Short shuffle chains (xor 1,2 inside aligned groups of 4) + wide ILP.
__global__ void node_kernel(const float* __restrict__ inp,
                            const float* __restrict__ y,
                            const void* mask, int N) {
    int tid  = blockIdx.x * blockDim.x + threadIdx.x;
    int node = tid >> 2;
    int sub  = tid & 3;
    if (node >= N) return;
    int mm = g_maskmode;

    const float4* ip = (const float4*)(inp + node * CC) + sub * 2;
    float4 a = ip[0], b = ip[1];

    float mx = fmaxf(fmaxf(fmaxf(a.x, a.y), fmaxf(a.z, a.w)),
                     fmaxf(fmaxf(b.x, b.y), fmaxf(b.z, b.w)));
    mx = fmaxf(mx, __shfl_xor_sync(0xffffffffu, mx, 1));
    mx = fmaxf(mx, __shfl_xor_sync(0xffffffffu, mx, 2));

    float e0 = __expf(a.x - mx), e1 = __expf(a.y - mx),
          e2 = __expf(a.z - mx), e3 = __expf(a.w - mx),
          e4 = __expf(b.x - mx), e5 = __expf(b.y - mx),
          e6 = __expf(b.z - mx), e7 = __expf(b.w - mx);
    float s = ((e0 + e1) + (e2 + e3)) + ((e4 + e5) + (e6 + e7));
    s += __shfl_xor_sync(0xffffffffu, s, 1);
    s += __shfl_xor_sync(0xffffffffu, s, 2);
    float inv = __frcp_rn(s);

    const float4* yp = (const float4*)(y + node * CC) + sub * 2;
    float4 ya = yp[0], yb = yp[1];

    bool mk = get_mask(mask, node, mm);
    float4 pa, pb;
    int labl = -1;
    if (mk) {
        pa = ya; pb = yb;
        int base = sub * 8;
        if (ya.x > 0.5f) labl = base + 0;
        if (ya.y > 0.5f) labl = base + 1;
        if (ya.z > 0.5f) labl = base + 2;
        if (ya.w > 0.5f) labl = base + 3;
        if (yb.x > 0.5f) labl = base + 4;
        if (yb.y > 0.5f) labl = base + 5;
        if (yb.z > 0.5f) labl = base + 6;
        if (yb.w > 0.5f) labl = base + 7;
    } else {
        pa = make_float4(e0 * inv, e1 * inv, e2 * inv, e3 * inv);
        pb = make_float4(e4 * inv, e5 * inv, e6 * inv, e7 * inv);
    }
    labl = max(labl, __shfl_xor_sync(0xffffffffu, labl, 1));
    labl = max(labl, __shfl_xor_sync(0xffffffffu, labl, 2));

    float4* op = (float4*)(g_p + node * CC) + sub * 2;
    op[0] = pa; op[1] = pb;

    if (sub == 0) {
        float d  = g_deg[node];
        float di = (d > 0.0f) ? rsqrtf(d) : 0.0f;
        g_info[node] = make_int2(__float_as_int(di), mk ? labl : -1);
        if (mk) atomicAdd(&g_cnt[labl], 1.0f);
    }
}

// Edge kernel. Entries [0,E) are edges; [E,E+N) self-loops (r=c, w=1).
// Masked row + masked col => p[col]=y[col] one-hot => SCALAR update via smem
// atomic. Masked row + unmasked col => vector broadcast path (packed shfl).
__global__ void edge_kernel(const int* __restrict__ row,
                            const int* __restrict__ col,
                            const float* __restrict__ w, int E, int N) {
    __shared__ float sH[8][CC * 33];
    int wid  = threadIdx.x >> 5;
    int lane = threadIdx.x & 31;
    float* mh = sH[wid];

    for (int k = threadIdx.x; k < 8 * CC * 33; k += blockDim.x)
        ((float*)sH)[k] = 0.0f;
    __syncthreads();

    int total  = E + N;
    int gw     = blockIdx.x * 8 + wid;
    int stride = gridDim.x * 8;

    for (int base = gw * 32; base < total; base += stride * 32) {
        int e = base + lane;
        int c = 0, a = -1, lc = -1;
        float v = 0.0f;
        if (e < total) {
            int r; float wt;
            if (e < E) { r = row[e]; c = col[e]; wt = w[e]; }
            else       { r = e - E; c = r;      wt = 1.0f; }
            int2 ir = g_info[r];
            a = ir.y;
            if (a >= 0) {
                int2 ic = g_info[c];
                lc = ic.y;
                v  = __int_as_float(ir.x) * wt * __int_as_float(ic.x);
            }
        }
        // scalar path: both endpoints masked -> single cell H[a][lc]
        if (a >= 0 && lc >= 0) atomicAdd(&mh[a * 33 + lc], v);
        // vector path: masked row, unmasked col -> full 32-wide p gather
        unsigned act = __ballot_sync(0xffffffffu, (a >= 0) & (lc < 0));
        int packed = (a << 20) | c;     // c < 2^17, a in [0,32)
        while (act) {
            int s = __ffs(act) - 1;
            act &= act - 1;
            int   pk = __shfl_sync(0xffffffffu, packed, s);
            float vs = __shfl_sync(0xffffffffu, v, s);
            float pv = g_p[(pk & 0xFFFFF) * CC + lane];   // coalesced 128B
            mh[(pk >> 20) * 33 + lane] += vs * pv;        // private tile
        }
    }
    __syncthreads();

    for (int k = threadIdx.x; k < CC * CC; k += blockDim.x) {
        int a = k >> 5, j = k & 31;
        float s = 0.0f;
        #pragma unroll
        for (int ww = 0; ww < 8; ww++) s += sH[ww][a * 33 + j];
        atomicAdd(&g_H[k], s);
    }
}

// Final: H = acc/cnt, NaN fixups, Sinkhorn to convergence (fixed point of the
// reference's 3000 iterations).
__global__ void final_kernel(float* __restrict__ out) {
    __shared__ float sm[CC * 33];
    __shared__ float sred[CC];
    __shared__ int   sflag;

    int i = threadIdx.x >> 5;   // row
    int j = threadIdx.x & 31;   // col (lane)

    float h = g_H[i * CC + j] / g_cnt[i];   // 0/0 -> NaN if empty class

    // Fixup 1: H = where(isnan(H), H^T, H)   (uses ORIGINAL H both sides)
    sm[j * 33 + i] = h;
    __syncthreads();
    float ht = sm[i * 33 + j];  // = H[j][i]
    if (isnan(h)) h = ht;
    __syncthreads();

    // Fixup 2: H0 = where(Hn,0,H); miss = (1-rowsum(H0))/rowcount(Hn)
    bool n2 = isnan(h);
    float h0 = n2 ? 0.0f : h;
    float rs = h0;
    float rn = n2 ? 1.0f : 0.0f;
    #pragma unroll
    for (int o = 16; o; o >>= 1) {
        rs += __shfl_xor_sync(0xffffffffu, rs, o);
        rn += __shfl_xor_sync(0xffffffffu, rn, o);
    }
    float miss = (1.0f - rs) / rn;
    h = n2 ? miss : h0;

    // Sinkhorn: col-normalize then row-normalize until converged (cap 3000)
    float hsave = h;
    for (int it = 0; it < 3000; it++) {
        sm[i * 33 + j] = h;
        __syncthreads();
        float vc = sm[j * 33 + i];          // warp i owns column i
        float cs = vc;
        #pragma unroll
        for (int o = 16; o; o >>= 1) cs += __shfl_xor_sync(0xffffffffu, cs, o);
        vc /= cs;
        sm[j * 33 + i] = vc;
        __syncthreads();
        h = sm[i * 33 + j];                 // back to row ownership
        float rs2 = h;
        #pragma unroll
        for (int o = 16; o; o >>= 1) rs2 += __shfl_xor_sync(0xffffffffu, rs2, o);
        h /= rs2;

        if ((it & 7) == 7) {
            float d = fabsf(h - hsave);
            #pragma unroll
            for (int o = 16; o; o >>= 1) d = fmaxf(d, __shfl_xor_sync(0xffffffffu, d, o));
            if (j == 0) sred[i] = d;
            __syncthreads();
            if (threadIdx.x == 0) {
                float m = 0.0f;
                for (int k = 0; k < CC; k++) m = fmaxf(m, sred[k]);
                sflag = (m < 1e-8f) ? 1 : 0;
            }
            __syncthreads();
            if (sflag) break;
            hsave = h;
        }
    }
    out[i * CC + j] = h;
}

// ---------------------------------------------------------------------------
extern "C" void kernel_launch(void* const* d_in, const int* in_sizes, int n_in,
                              void* d_out, int out_size) {
    const int*   ei   = (const int*)d_in[0];    // edge_index (2,E)
    const float* ew   = (const float*)d_in[1];  // edge_weight (E,)
    const float* inp  = (const float*)d_in[2];  // inputs (N,32)
    const float* y    = (const float*)d_in[3];  // y (N,32)
    const void*  mask = d_in[4];                // sample_mask (N,)

    int E = in_sizes[1];
    int N = in_sizes[2] / CC;
    const int* rowp = ei;
    const int* colp = ei + E;

    zero_detect_kernel<<<(N + 255) / 256, 256>>>(mask, N);
    deg_kernel<<<(E + N + 255) / 256, 256>>>(rowp, ew, E, N);
    node_kernel<<<(N * 4 + 255) / 256, 256>>>(inp, y, mask, N);
    edge_kernel<<<888, 256>>>(rowp, colp, ew, E, N);
    final_kernel<<<1, 1024>>>((float*)d_out);
}